// round 7
// baseline (speedup 1.0000x reference)
#include <cuda_runtime.h>
#include <math.h>
#include <cstdint>

#define N_NODES 100000
#define E_EDGES 800000
#define D 128
#define EPSV 1e-4f
#define LN_EPSV 1e-5f

#define SCAN_B 512
#define NBLK ((N_NODES + SCAN_B - 1) / SCAN_B)   // 196

#define TILE_M 128
#define MM_CTAS ((N_NODES + TILE_M - 1) / TILE_M)  // 782
#define MM_THREADS 512

// ---- scratch (device globals; no allocation allowed) ----
__device__ float   g_h[(size_t)N_NODES * D];
__device__ float   g_rate[(size_t)N_NODES * D];
__device__ float   g_gamma[(size_t)N_NODES * D];
__device__ int     g_cnt[N_NODES];
__device__ int     g_cur[N_NODES];
__device__ int     g_off[N_NODES];
__device__ int     g_bsum[NBLK];
__device__ int     g_ecol[E_EDGES];
// int8-split transposed weights: [mat][n(128)][k(128)] bytes, hi and lo parts
__device__ uint8_t g_w1[3 * 128 * 128];
__device__ uint8_t g_w2[3 * 128 * 128];
__device__ float   g_sw[3 * 128];

// ============================ helpers ============================
__device__ __forceinline__ uint32_t smem_u32(const void* p) {
    uint32_t a;
    asm("{ .reg .u64 t; cvta.to.shared.u64 t, %1; cvt.u32.u64 %0, t; }" : "=r"(a) : "l"(p));
    return a;
}

__device__ __forceinline__ void ldmatrix4(uint32_t* r, uint32_t addr) {
    asm volatile("ldmatrix.sync.aligned.m8n8.x4.shared.b16 {%0,%1,%2,%3}, [%4];"
                 : "=r"(r[0]), "=r"(r[1]), "=r"(r[2]), "=r"(r[3]) : "r"(addr));
}

__device__ __forceinline__ void mma_s8(int32_t* c, const uint32_t* a, uint32_t b0, uint32_t b1) {
    asm volatile("mma.sync.aligned.m16n8k32.row.col.s32.s8.s8.s32 "
                 "{%0,%1,%2,%3}, {%4,%5,%6,%7}, {%8,%9}, {%0,%1,%2,%3};"
                 : "+r"(c[0]), "+r"(c[1]), "+r"(c[2]), "+r"(c[3])
                 : "r"(a[0]), "r"(a[1]), "r"(a[2]), "r"(a[3]), "r"(b0), "r"(b1));
}

__device__ __forceinline__ void cp_async16(uint32_t saddr, const void* gaddr) {
    asm volatile("cp.async.cg.shared.global [%0], [%1], 16;" :: "r"(saddr), "l"(gaddr));
}
__device__ __forceinline__ void cp_commit() { asm volatile("cp.async.commit_group;"); }
__device__ __forceinline__ void cp_wait0()  { asm volatile("cp.async.wait_group 0;" ::: "memory"); }

// split Q (|Q| <= ~32100) into X1*256 + X2, X1,X2 in s8 range
__device__ __forceinline__ void split15(float v, float kx, int& x1, int& x2) {
    int q = __float2int_rn(v * kx);
    x1 = (q + 128) >> 8;          // arithmetic shift = floor((q+128)/256)
    x2 = q - (x1 << 8);
}

// ============================ small kernels ============================
__global__ void k_zero() {
    int i = blockIdx.x * blockDim.x + threadIdx.x;
    if (i < N_NODES) g_cnt[i] = 0;
}

__global__ void k_count(const int* __restrict__ row) {
    int e = blockIdx.x * blockDim.x + threadIdx.x;
    if (e < E_EDGES) atomicAdd(&g_cnt[row[e]], 1);
}

__global__ __launch_bounds__(SCAN_B) void k_scan1() {
    __shared__ int wsum[SCAN_B / 32];
    int i = blockIdx.x * SCAN_B + threadIdx.x;
    int lane = threadIdx.x & 31, wid = threadIdx.x >> 5;
    int v = (i < N_NODES) ? g_cnt[i] : 0;
    if (i < N_NODES) g_cur[i] = 0;
    int s = v;
    #pragma unroll
    for (int o = 1; o < 32; o <<= 1) { int t = __shfl_up_sync(~0u, s, o); if (lane >= o) s += t; }
    if (lane == 31) wsum[wid] = s;
    __syncthreads();
    if (wid == 0) {
        int ws = (lane < SCAN_B / 32) ? wsum[lane] : 0;
        #pragma unroll
        for (int o = 1; o < SCAN_B / 32; o <<= 1) { int t = __shfl_up_sync(~0u, ws, o); if (lane >= o) ws += t; }
        if (lane < SCAN_B / 32) wsum[lane] = ws;
    }
    __syncthreads();
    int base = (wid > 0) ? wsum[wid - 1] : 0;
    if (i < N_NODES) g_off[i] = base + s - v;
    if (threadIdx.x == SCAN_B - 1) g_bsum[blockIdx.x] = base + s;
}

__global__ __launch_bounds__(256) void k_scan2() {
    __shared__ int wsum[8];
    int lane = threadIdx.x & 31, wid = threadIdx.x >> 5;
    int v = (threadIdx.x < NBLK) ? g_bsum[threadIdx.x] : 0;
    int s = v;
    #pragma unroll
    for (int o = 1; o < 32; o <<= 1) { int t = __shfl_up_sync(~0u, s, o); if (lane >= o) s += t; }
    if (lane == 31) wsum[wid] = s;
    __syncthreads();
    if (wid == 0) {
        int ws = (lane < 8) ? wsum[lane] : 0;
        #pragma unroll
        for (int o = 1; o < 8; o <<= 1) { int t = __shfl_up_sync(~0u, ws, o); if (lane >= o) ws += t; }
        if (lane < 8) wsum[lane] = ws;
    }
    __syncthreads();
    int base = (wid > 0) ? wsum[wid - 1] : 0;
    if (threadIdx.x < NBLK) g_bsum[threadIdx.x] = base + s - v;
}

__global__ __launch_bounds__(256) void k_bin(const int* __restrict__ row, const int* __restrict__ col) {
    int e = blockIdx.x * blockDim.x + threadIdx.x;
    if (e >= E_EDGES) return;
    int r = row[e];
    int pos = g_off[r] + g_bsum[r >> 9] + atomicAdd(&g_cur[r], 1);
    g_ecol[pos] = col[e];
}

// ---- pre-transpose + int8-split W: per-column 15-bit fixed point ----
__global__ __launch_bounds__(256) void k_wsplit(const float* __restrict__ W_fc,
                                                const float* __restrict__ W_rate,
                                                const float* __restrict__ W_rob) {
    int t = blockIdx.x * blockDim.x + threadIdx.x;   // 3*128*32 = 12288
    if (t >= 3 * 128 * 32) return;
    int mat = t >> 12;
    int n = (t & 4095) >> 5;
    int lane = t & 31;
    int k0 = lane << 2;
    const float* W = (mat == 0) ? W_fc : ((mat == 1) ? W_rate : W_rob);
    float v[4];
    #pragma unroll
    for (int i = 0; i < 4; i++) v[i] = W[(size_t)(k0 + i) * D + n];
    float am = fmaxf(fmaxf(fabsf(v[0]), fabsf(v[1])), fmaxf(fabsf(v[2]), fabsf(v[3])));
    #pragma unroll
    for (int o = 16; o > 0; o >>= 1) am = fmaxf(am, __shfl_xor_sync(~0u, am, o));
    am = fmaxf(am, 1e-20f);
    float kw = 32000.f / am;
    uint32_t w1 = 0, w2 = 0;
    #pragma unroll
    for (int i = 0; i < 4; i++) {
        int x1, x2;
        split15(v[i], kw, x1, x2);
        w1 |= (uint32_t)(x1 & 0xFF) << (i * 8);
        w2 |= (uint32_t)(x2 & 0xFF) << (i * 8);
    }
    size_t o8 = (size_t)mat * 16384 + n * 128 + k0;
    *(uint32_t*)(g_w1 + o8) = w1;
    *(uint32_t*)(g_w2 + o8) = w2;
    if (lane == 0) g_sw[mat * 128 + n] = am;
}

// ============================ int8 mma fused 3x GEMM ============================
// TILE_M=128, 512 threads = 16 warps (8 M-groups x 2 N-groups), warp tile 16x64.
// smem rows: 128 bytes (K=128 s8), 16B-unit swizzle u -> u ^ (row & 7).
#define SM_X1 0
#define SM_X2 16384
#define SM_W1 32768
#define SM_W2 49152
#define SM_SX 65536
#define SM_SW 66048
#define SM_TOTAL 66560

#define MM_PASS(ABASE, BBASE, ACC) \
    for (int kc = 0; kc < 4; kc++) { \
        uint32_t a[4]; \
        ldmatrix4(a, sbase + (ABASE) + aOff + (((kc * 2 + aKh) ^ aSw) << 4)); \
        uint32_t b[4][4]; \
        b[0][0]=b[0][1]=0; \
        ldmatrix4(b[0], sbase + (BBASE) + bOff0 + (((kc * 2 + bKh) ^ bSw0) << 4)); \
        ldmatrix4(b[1], sbase + (BBASE) + bOff1 + (((kc * 2 + bKh) ^ bSw1) << 4)); \
        ldmatrix4(b[2], sbase + (BBASE) + bOff2 + (((kc * 2 + bKh) ^ bSw2) << 4)); \
        ldmatrix4(b[3], sbase + (BBASE) + bOff3 + (((kc * 2 + bKh) ^ bSw3) << 4)); \
        _Pragma("unroll") \
        for (int nt = 0; nt < 8; nt++) \
            mma_s8(ACC[nt], a, b[nt >> 1][(nt & 1) * 2], b[nt >> 1][(nt & 1) * 2 + 1]); \
    }

__global__ __launch_bounds__(MM_THREADS) void k_mm(const float* __restrict__ x,
                                                   const float* __restrict__ b_fc,
                                                   const float* __restrict__ b_rob) {
    extern __shared__ char smem[];
    const uint32_t sbase = smem_u32(smem);
    float* sx_s = (float*)(smem + SM_SX);
    float* sw_s = (float*)(smem + SM_SW);
    const int tid = threadIdx.x;
    const int wid = tid >> 5;
    const int lane = tid & 31;
    const int m0 = blockIdx.x * TILE_M;
    const int warpM = wid & 7;     // rows 16*warpM .. +16
    const int warpN = wid >> 3;    // cols 64*warpN .. +64

    // ---- kick off W[0] + sw[0] loads ----
    #pragma unroll
    for (int r = 0; r < 4; r++) {
        int idx = (r << 9) + tid;   // 0..2047 -> W1 then W2 (1024 units each)
        int h = idx >> 10;
        int rem = idx & 1023;
        int n = rem >> 3;
        int u = rem & 7;
        uint32_t dst = sbase + (h ? SM_W2 : SM_W1) + (uint32_t)(n * 128 + ((u ^ (n & 7)) << 4));
        const uint8_t* src = (h ? g_w2 : g_w1) + (size_t)n * 128 + (u << 4);
        cp_async16(dst, src);
    }
    if (tid < 32) cp_async16(sbase + SM_SW + tid * 16, (const char*)g_sw + tid * 16);
    cp_commit();

    // ---- stage x tile: per-row 15-bit quantize + split, swizzled store ----
    #pragma unroll
    for (int r = 0; r < 8; r++) {
        int idx = (r << 9) + tid;           // 0..4095
        int m = idx >> 5;                   // one row per warp-iteration
        int kq = idx & 31;                  // == lane
        float4 v = make_float4(0.f, 0.f, 0.f, 0.f);
        if (m0 + m < N_NODES) v = *(const float4*)(x + (size_t)(m0 + m) * D + (kq << 2));
        float am = fmaxf(fmaxf(fabsf(v.x), fabsf(v.y)), fmaxf(fabsf(v.z), fabsf(v.w)));
        #pragma unroll
        for (int o = 16; o > 0; o >>= 1) am = fmaxf(am, __shfl_xor_sync(~0u, am, o));
        am = fmaxf(am, 1e-20f);
        float kx = 32000.f / am;
        const float* vp = (const float*)&v;
        uint32_t w1 = 0, w2 = 0;
        #pragma unroll
        for (int i = 0; i < 4; i++) {
            int x1, x2;
            split15(vp[i], kx, x1, x2);
            w1 |= (uint32_t)(x1 & 0xFF) << (i * 8);
            w2 |= (uint32_t)(x2 & 0xFF) << (i * 8);
        }
        uint32_t addr = (uint32_t)(m * 128 + (((kq >> 2) ^ (m & 7)) << 4) + (kq & 3) * 4);
        *(uint32_t*)(smem + SM_X1 + addr) = w1;
        *(uint32_t*)(smem + SM_X2 + addr) = w2;
        if (kq == 0) sx_s[m] = am;
    }
    cp_wait0();
    __syncthreads();

    // ---- per-thread ldmatrix address components ----
    const int quad = lane >> 3;
    const int l8 = lane & 7;
    // A tiles: quad0 rows0-7 h0, quad1 rows8-15 h0, quad2 rows0-7 h1, quad3 rows8-15 h1
    const int aRow = warpM * 16 + (quad & 1) * 8 + l8;
    const uint32_t aOff = aRow * 128;
    const int aSw = aRow & 7;
    const int aKh = quad >> 1;
    // B tiles for x4 #q: quad0 ng=2q h0, quad1 ng=2q h1, quad2 ng=2q+1 h0, quad3 ng=2q+1 h1
    const int bKh = quad & 1;
    const int bgo = quad >> 1;
    const int bRow0 = warpN * 64 + (0 + bgo) * 8 + l8;
    const int bRow1 = warpN * 64 + (2 + bgo) * 8 + l8;
    const int bRow2 = warpN * 64 + (4 + bgo) * 8 + l8;
    const int bRow3 = warpN * 64 + (6 + bgo) * 8 + l8;
    const uint32_t bOff0 = bRow0 * 128; const int bSw0 = bRow0 & 7;
    const uint32_t bOff1 = bRow1 * 128; const int bSw1 = bRow1 & 7;
    const uint32_t bOff2 = bRow2 * 128; const int bSw2 = bRow2 & 7;
    const uint32_t bOff3 = bRow3 * 128; const int bSw3 = bRow3 & 7;

    const int g4 = lane >> 2;
    const int t4 = lane & 3;
    const float INV = 1.0f / (32000.f * 32000.f);

    for (int mat = 0; mat < 3; mat++) {
        int32_t acc_hi[8][4], acc_mid[8][4];
        #pragma unroll
        for (int nt = 0; nt < 8; nt++)
            #pragma unroll
            for (int i = 0; i < 4; i++) { acc_hi[nt][i] = 0; acc_mid[nt][i] = 0; }

        MM_PASS(SM_X1, SM_W1, acc_hi)    // X1*W1
        MM_PASS(SM_X1, SM_W2, acc_mid)   // X1*W2
        MM_PASS(SM_X2, SM_W1, acc_mid)   // X2*W1  (shared scale with X1*W2)

        // scales for this thread's fragment
        float sxa = sx_s[warpM * 16 + g4];
        float sxb = sx_s[warpM * 16 + 8 + g4];
        float swv[8][2];
        #pragma unroll
        for (int nt = 0; nt < 8; nt++) {
            int col = warpN * 64 + nt * 8 + t4 * 2;
            swv[nt][0] = sw_s[col];
            swv[nt][1] = sw_s[col + 1];
        }

        // prefetch next W while epilogue runs
        if (mat < 2) {
            __syncthreads();   // everyone done reading W[mat]
            #pragma unroll
            for (int r = 0; r < 4; r++) {
                int idx = (r << 9) + tid;
                int h = idx >> 10;
                int rem = idx & 1023;
                int n = rem >> 3;
                int u = rem & 7;
                uint32_t dst = sbase + (h ? SM_W2 : SM_W1) + (uint32_t)(n * 128 + ((u ^ (n & 7)) << 4));
                const uint8_t* src = (h ? g_w2 : g_w1) + (size_t)(mat + 1) * 16384 + (size_t)n * 128 + (u << 4);
                cp_async16(dst, src);
            }
            if (tid < 32) cp_async16(sbase + SM_SW + tid * 16,
                                     (const char*)g_sw + (mat + 1) * 512 + tid * 16);
            cp_commit();
        }

        // ---- epilogue ----
        {
            float* outp = (mat == 0) ? g_h : ((mat == 1) ? g_rate : g_gamma);
            const float* bias = (mat == 0) ? b_fc : b_rob;
            int r0 = m0 + warpM * 16 + g4;
            int r1 = r0 + 8;
            #pragma unroll
            for (int nt = 0; nt < 8; nt++) {
                int col = warpN * 64 + nt * 8 + t4 * 2;
                float s0a = sxa * swv[nt][0] * INV;
                float s1a = sxa * swv[nt][1] * INV;
                float s0b = sxb * swv[nt][0] * INV;
                float s1b = sxb * swv[nt][1] * INV;
                float v0 = fmaf(65536.f, (float)acc_hi[nt][0], 256.f * (float)acc_mid[nt][0]) * s0a;
                float v1 = fmaf(65536.f, (float)acc_hi[nt][1], 256.f * (float)acc_mid[nt][1]) * s1a;
                float v2 = fmaf(65536.f, (float)acc_hi[nt][2], 256.f * (float)acc_mid[nt][2]) * s0b;
                float v3 = fmaf(65536.f, (float)acc_hi[nt][3], 256.f * (float)acc_mid[nt][3]) * s1b;
                if (mat == 1) {
                    v0 = ((v0 > 20.f) ? v0 : log1pf(__expf(v0))) + EPSV;
                    v1 = ((v1 > 20.f) ? v1 : log1pf(__expf(v1))) + EPSV;
                    v2 = ((v2 > 20.f) ? v2 : log1pf(__expf(v2))) + EPSV;
                    v3 = ((v3 > 20.f) ? v3 : log1pf(__expf(v3))) + EPSV;
                } else {
                    float b0 = bias[col], b1 = bias[col + 1];
                    v0 += b0; v1 += b1; v2 += b0; v3 += b1;
                }
                if (r0 < N_NODES) *(float2*)(outp + (size_t)r0 * D + col) = make_float2(v0, v1);
                if (r1 < N_NODES) *(float2*)(outp + (size_t)r1 * D + col) = make_float2(v2, v3);
            }
        }

        if (mat < 2) { cp_wait0(); __syncthreads(); }
    }
}

// ---------------- fused gather + combine + LayerNorm (one warp per node) ----
__global__ __launch_bounds__(256) void k_final(const int* __restrict__ degree,
                                               const float* __restrict__ ln_g,
                                               const float* __restrict__ ln_b,
                                               float* __restrict__ out)
{
    int w = (blockIdx.x * blockDim.x + threadIdx.x) >> 5;
    int lane = threadIdx.x & 31;
    if (w >= N_NODES) return;
    size_t base = (size_t)w * D;

    int start = g_off[w] + g_bsum[w >> 9];
    int cnt = g_cnt[w];

    float4 acc = make_float4(0.f, 0.f, 0.f, 0.f);
    int j = 0;
    for (; j + 4 <= cnt; j += 4) {
        int c0 = g_ecol[start + j + 0];
        int c1 = g_ecol[start + j + 1];
        int c2 = g_ecol[start + j + 2];
        int c3 = g_ecol[start + j + 3];
        float4 v0 = __ldg(((const float4*)(g_h + (size_t)c0 * D)) + lane);
        float4 v1 = __ldg(((const float4*)(g_h + (size_t)c1 * D)) + lane);
        float4 v2 = __ldg(((const float4*)(g_h + (size_t)c2 * D)) + lane);
        float4 v3 = __ldg(((const float4*)(g_h + (size_t)c3 * D)) + lane);
        acc.x += (v0.x + v1.x) + (v2.x + v3.x);
        acc.y += (v0.y + v1.y) + (v2.y + v3.y);
        acc.z += (v0.z + v1.z) + (v2.z + v3.z);
        acc.w += (v0.w + v1.w) + (v2.w + v3.w);
    }
    for (; j < cnt; j++) {
        int c = g_ecol[start + j];
        float4 v = __ldg(((const float4*)(g_h + (size_t)c * D)) + lane);
        acc.x += v.x; acc.y += v.y; acc.z += v.z; acc.w += v.w;
    }

    float4 h4 = ((const float4*)(g_h + base))[lane];
    float4 r4 = ((const float4*)(g_rate + base))[lane];
    float4 g4 = ((const float4*)(g_gamma + base))[lane];
    float fc = (float)cnt;
    float deg = (float)degree[w];

    float y[4];
    {
        const float* hp = (const float*)&h4;
        const float* ap = (const float*)&acc;
        const float* rp = (const float*)&r4;
        const float* gp = (const float*)&g4;
        #pragma unroll
        for (int i = 0; i < 4; i++) {
            float agg_full = ap[i] + fc * hp[i];
            y[i] = (rp[i] * agg_full + gp[i]) / (1.0f + EPSV + rp[i] * deg);
        }
    }

    float s = y[0] + y[1] + y[2] + y[3];
    float s2 = y[0]*y[0] + y[1]*y[1] + y[2]*y[2] + y[3]*y[3];
    #pragma unroll
    for (int off = 16; off > 0; off >>= 1) {
        s  += __shfl_xor_sync(0xffffffffu, s,  off);
        s2 += __shfl_xor_sync(0xffffffffu, s2, off);
    }
    float mean = s * (1.0f / D);
    float var = s2 * (1.0f / D) - mean * mean;
    float rstd = rsqrtf(var + LN_EPSV);

    float4 lg = ((const float4*)ln_g)[lane];
    float4 lb = ((const float4*)ln_b)[lane];
    float4 o;
    o.x = (y[0] - mean) * rstd * lg.x + lb.x;
    o.y = (y[1] - mean) * rstd * lg.y + lb.y;
    o.z = (y[2] - mean) * rstd * lg.z + lb.z;
    o.w = (y[3] - mean) * rstd * lg.w + lb.w;
    ((float4*)(out + base))[lane] = o;
}

// ---------------- launch ----------------
extern "C" void kernel_launch(void* const* d_in, const int* in_sizes, int n_in,
                              void* d_out, int out_size) {
    const float* x      = (const float*)d_in[0];
    const int*   ei     = (const int*)  d_in[1];
    const int*   degree = (const int*)  d_in[2];
    const float* W_fc   = (const float*)d_in[3];
    const float* b_fc   = (const float*)d_in[4];
    const float* W_rate = (const float*)d_in[5];
    const float* W_rob  = (const float*)d_in[6];
    const float* b_rob  = (const float*)d_in[7];
    const float* ln_g   = (const float*)d_in[8];
    const float* ln_b   = (const float*)d_in[9];
    float* out = (float*)d_out;

    const int* row = ei;             // edge_index[0]
    const int* col = ei + E_EDGES;   // edge_index[1]

    cudaFuncSetAttribute(k_mm, cudaFuncAttributeMaxDynamicSharedMemorySize, SM_TOTAL);

    k_zero<<<(N_NODES + 255) / 256, 256>>>();
    k_count<<<(E_EDGES + 255) / 256, 256>>>(row);
    k_wsplit<<<(3 * 128 * 32 + 255) / 256, 256>>>(W_fc, W_rate, W_rob);
    k_scan1<<<NBLK, SCAN_B>>>();
    k_scan2<<<1, 256>>>();
    k_bin<<<(E_EDGES + 255) / 256, 256>>>(row, col);
    k_mm<<<MM_CTAS, MM_THREADS, SM_TOTAL>>>(x, b_fc, b_rob);
    k_final<<<(int)(((size_t)N_NODES * 32 + 255) / 256), 256>>>(degree, ln_g, ln_b, out);
}

// round 8
// speedup vs baseline: 2.0953x; 2.0953x over previous
#include <cuda_runtime.h>
#include <cuda_fp16.h>
#include <math.h>
#include <cstdint>

#define N_NODES 100000
#define E_EDGES 800000
#define D 128
#define EPSV 1e-4f
#define LN_EPSV 1e-5f

#define SCAN_B 512
#define NBLK ((N_NODES + SCAN_B - 1) / SCAN_B)   // 196

#define TILE_M 256
#define MM_CTAS ((N_NODES + TILE_M - 1) / TILE_M)  // 391
#define MM_THREADS 512

// ---- scratch (device globals; no allocation allowed) ----
__device__ float  g_h[(size_t)N_NODES * D];
__device__ float  g_rate[(size_t)N_NODES * D];
__device__ float  g_gamma[(size_t)N_NODES * D];
__device__ int    g_cnt[N_NODES];
__device__ int    g_cur[N_NODES];
__device__ int    g_off[N_NODES];
__device__ int    g_bsum[NBLK];
__device__ int    g_ecol[E_EDGES];
// fp16-split, transposed weights: [mat(3)][hi/lo(2)][n(128)][k(128)] halves
__device__ __half g_wh[3 * 2 * 128 * 128];

// ============================ helpers ============================
__device__ __forceinline__ uint32_t smem_u32(const void* p) {
    uint32_t a;
    asm("{ .reg .u64 t; cvta.to.shared.u64 t, %1; cvt.u32.u64 %0, t; }" : "=r"(a) : "l"(p));
    return a;
}

__device__ __forceinline__ void ldmatrix4(uint32_t* r, uint32_t addr) {
    asm volatile("ldmatrix.sync.aligned.m8n8.x4.shared.b16 {%0,%1,%2,%3}, [%4];"
                 : "=r"(r[0]), "=r"(r[1]), "=r"(r[2]), "=r"(r[3]) : "r"(addr));
}

__device__ __forceinline__ void mma16816(float* c, const uint32_t* a, uint32_t b0, uint32_t b1) {
    asm volatile("mma.sync.aligned.m16n8k16.row.col.f32.f16.f16.f32 "
                 "{%0,%1,%2,%3}, {%4,%5,%6,%7}, {%8,%9}, {%0,%1,%2,%3};"
                 : "+f"(c[0]), "+f"(c[1]), "+f"(c[2]), "+f"(c[3])
                 : "r"(a[0]), "r"(a[1]), "r"(a[2]), "r"(a[3]), "r"(b0), "r"(b1));
}

__device__ __forceinline__ void cp_async16(uint32_t saddr, const void* gaddr) {
    asm volatile("cp.async.cg.shared.global [%0], [%1], 16;" :: "r"(saddr), "l"(gaddr));
}
__device__ __forceinline__ void cp_commit() { asm volatile("cp.async.commit_group;"); }
__device__ __forceinline__ void cp_wait0()  { asm volatile("cp.async.wait_group 0;" ::: "memory"); }

// ============================ small kernels ============================
__global__ void k_zero() {
    int i = blockIdx.x * blockDim.x + threadIdx.x;
    if (i < N_NODES) g_cnt[i] = 0;
}

__global__ void k_count(const int* __restrict__ row) {
    int e = blockIdx.x * blockDim.x + threadIdx.x;
    if (e < E_EDGES) atomicAdd(&g_cnt[row[e]], 1);
}

__global__ __launch_bounds__(SCAN_B) void k_scan1() {
    __shared__ int wsum[SCAN_B / 32];
    int i = blockIdx.x * SCAN_B + threadIdx.x;
    int lane = threadIdx.x & 31, wid = threadIdx.x >> 5;
    int v = (i < N_NODES) ? g_cnt[i] : 0;
    if (i < N_NODES) g_cur[i] = 0;
    int s = v;
    #pragma unroll
    for (int o = 1; o < 32; o <<= 1) { int t = __shfl_up_sync(~0u, s, o); if (lane >= o) s += t; }
    if (lane == 31) wsum[wid] = s;
    __syncthreads();
    if (wid == 0) {
        int ws = (lane < SCAN_B / 32) ? wsum[lane] : 0;
        #pragma unroll
        for (int o = 1; o < SCAN_B / 32; o <<= 1) { int t = __shfl_up_sync(~0u, ws, o); if (lane >= o) ws += t; }
        if (lane < SCAN_B / 32) wsum[lane] = ws;
    }
    __syncthreads();
    int base = (wid > 0) ? wsum[wid - 1] : 0;
    if (i < N_NODES) g_off[i] = base + s - v;
    if (threadIdx.x == SCAN_B - 1) g_bsum[blockIdx.x] = base + s;
}

__global__ __launch_bounds__(256) void k_scan2() {
    __shared__ int wsum[8];
    int lane = threadIdx.x & 31, wid = threadIdx.x >> 5;
    int v = (threadIdx.x < NBLK) ? g_bsum[threadIdx.x] : 0;
    int s = v;
    #pragma unroll
    for (int o = 1; o < 32; o <<= 1) { int t = __shfl_up_sync(~0u, s, o); if (lane >= o) s += t; }
    if (lane == 31) wsum[wid] = s;
    __syncthreads();
    if (wid == 0) {
        int ws = (lane < 8) ? wsum[lane] : 0;
        #pragma unroll
        for (int o = 1; o < 8; o <<= 1) { int t = __shfl_up_sync(~0u, ws, o); if (lane >= o) ws += t; }
        if (lane < 8) wsum[lane] = ws;
    }
    __syncthreads();
    int base = (wid > 0) ? wsum[wid - 1] : 0;
    if (threadIdx.x < NBLK) g_bsum[threadIdx.x] = base + s - v;
}

// bin: pos = local_off + block_base + rank (scan3 folded in)
__global__ __launch_bounds__(256) void k_bin(const int* __restrict__ row, const int* __restrict__ col) {
    int e = blockIdx.x * blockDim.x + threadIdx.x;
    if (e >= E_EDGES) return;
    int r = row[e];
    int pos = g_off[r] + g_bsum[r >> 9] + atomicAdd(&g_cur[r], 1);
    g_ecol[pos] = col[e];
}

// ---- pre-transpose + fp16-split W into g_wh[mat][hi/lo][n][k] ----
__global__ __launch_bounds__(256) void k_wsplit(const float* __restrict__ W_fc,
                                                const float* __restrict__ W_rate,
                                                const float* __restrict__ W_rob) {
    int t = blockIdx.x * blockDim.x + threadIdx.x;   // 3*128*32 = 12288
    if (t >= 3 * 128 * 32) return;
    int mat = t >> 12;
    int n = (t & 4095) >> 5;
    int k0 = (t & 31) << 2;
    const float* W = (mat == 0) ? W_fc : ((mat == 1) ? W_rate : W_rob);
    __half hi[4], lo[4];
    #pragma unroll
    for (int i = 0; i < 4; i++) {
        float v = W[(size_t)(k0 + i) * D + n];
        __half h = __float2half_rn(v);
        hi[i] = h;
        lo[i] = __float2half_rn(v - __half2float(h));
    }
    size_t oh = ((size_t)(mat * 2 + 0) << 14) + (n << 7) + k0;
    size_t ol = ((size_t)(mat * 2 + 1) << 14) + (n << 7) + k0;
    *(uint2*)(g_wh + oh) = *(uint2*)hi;
    *(uint2*)(g_wh + ol) = *(uint2*)lo;
}

// ============================ mma.sync fused 3x GEMM ============================
// TILE_M=256, 512 threads (16 warps: 8 M-groups x 2 N-groups).
// smem: x_hi [0,64K)  x_lo [64K,128K)  Wbuf [128K,192K) single-buffered
// fp16 [row][k] rows of 256B, 16B-unit swizzle: unit u -> u ^ (row & 7).
#define SM_XHI   0
#define SM_XLO   65536
#define SM_WB    131072
#define SM_TOTAL (131072 + 65536)   // 196608

__global__ __launch_bounds__(MM_THREADS, 1) void k_mm(const float* __restrict__ x,
                                                      const float* __restrict__ b_fc,
                                                      const float* __restrict__ b_rob) {
    extern __shared__ char smem[];
    const uint32_t sbase = smem_u32(smem);
    const int tid = threadIdx.x;
    const int wid = tid >> 5;
    const int lane = tid & 31;
    const int m0 = blockIdx.x * TILE_M;
    const int warpM = wid & 7;     // rows 32*warpM .. +32
    const int warpN = wid >> 3;    // cols 64*warpN .. +64

    // ---- stage x tile as fp16 hi/lo (256 rows x 128 k) ----
    #pragma unroll
    for (int r = 0; r < 16; r++) {
        int idx = (r << 9) + tid;           // 0..8191
        int m = idx >> 5;
        int kq = idx & 31;                  // float4 index; k0 = kq*4
        float4 v = make_float4(0.f, 0.f, 0.f, 0.f);
        if (m0 + m < N_NODES) v = *(const float4*)(x + (size_t)(m0 + m) * D + (kq << 2));
        __half hx = __float2half_rn(v.x), hy = __float2half_rn(v.y);
        __half hz = __float2half_rn(v.z), hw = __float2half_rn(v.w);
        __half lx = __float2half_rn(v.x - __half2float(hx));
        __half ly = __float2half_rn(v.y - __half2float(hy));
        __half lz = __float2half_rn(v.z - __half2float(hz));
        __half lw = __float2half_rn(v.w - __half2float(hw));
        uint2 hp, lp;
        hp.x = __half_as_ushort(hx) | ((uint32_t)__half_as_ushort(hy) << 16);
        hp.y = __half_as_ushort(hz) | ((uint32_t)__half_as_ushort(hw) << 16);
        lp.x = __half_as_ushort(lx) | ((uint32_t)__half_as_ushort(ly) << 16);
        lp.y = __half_as_ushort(lz) | ((uint32_t)__half_as_ushort(lw) << 16);
        int u = kq >> 1;                    // 16B unit
        int off8 = (kq & 1) << 3;
        uint32_t so = (uint32_t)(m * 256 + ((u ^ (m & 7)) << 4) + off8);
        *(uint2*)(smem + SM_XHI + so) = hp;
        *(uint2*)(smem + SM_XLO + so) = lp;
    }

    // ---- prefetch W[0] (hi+lo, 64KB = 4096 16B units, 8 per thread) ----
    {
        const char* wsrc = (const char*)g_wh;
        #pragma unroll
        for (int r = 0; r < 8; r++) {
            int idx = (r << 9) + tid;           // 0..4095
            int h = idx >> 11;
            int rem = idx & 2047;
            int n = rem >> 4;
            int u = rem & 15;
            uint32_t dst = sbase + SM_WB + (h << 15) + (uint32_t)(n * 256 + ((u ^ (n & 7)) << 4));
            cp_async16(dst, wsrc + ((size_t)h << 15) + (size_t)n * 256 + (u << 4));
        }
        cp_commit();
    }
    cp_wait0();
    __syncthreads();

    // per-thread ldmatrix address components
    const int rowA_off = (lane & 7) + (((lane >> 3) & 1) << 3);
    const int dA = lane >> 4;
    const int nB_off = (lane & 7) + (((lane >> 4) & 1) << 3);
    const int dB = (lane >> 3) & 1;

    int rowA[2], s7A[2];
    #pragma unroll
    for (int mt = 0; mt < 2; mt++) {
        int rr = warpM * 32 + mt * 16 + rowA_off;
        rowA[mt] = rr * 256; s7A[mt] = rr & 7;
    }
    int rowB[4], s7B[4];
    #pragma unroll
    for (int nt2 = 0; nt2 < 4; nt2++) {
        int nn = warpN * 64 + nt2 * 16 + nB_off;
        rowB[nt2] = nn * 256; s7B[nt2] = nn & 7;
    }

    const int g4 = lane >> 2;      // C-frag row within tile
    const int t4 = lane & 3;       // C-frag col pair

    for (int mat = 0; mat < 3; mat++) {
        float acc[2][8][4];
        #pragma unroll
        for (int mt = 0; mt < 2; mt++)
            #pragma unroll
            for (int nt = 0; nt < 8; nt++)
                #pragma unroll
                for (int i = 0; i < 4; i++) acc[mt][nt][i] = 0.f;

        #pragma unroll 1
        for (int term = 0; term < 3; term++) {
            const uint32_t abase = sbase + ((term == 2) ? SM_XLO : SM_XHI);
            const uint32_t bbase = sbase + SM_WB + ((term == 1) ? 32768u : 0u);
            #pragma unroll 1
            for (int ks = 0; ks < 8; ks++) {
                uint32_t a[2][4];
                #pragma unroll
                for (int mt = 0; mt < 2; mt++) {
                    int u = 2 * ks + dA;
                    ldmatrix4(a[mt], abase + rowA[mt] + ((u ^ s7A[mt]) << 4));
                }
                uint32_t b[4][4];
                #pragma unroll
                for (int nt2 = 0; nt2 < 4; nt2++) {
                    int u = 2 * ks + dB;
                    ldmatrix4(b[nt2], bbase + rowB[nt2] + ((u ^ s7B[nt2]) << 4));
                }
                #pragma unroll
                for (int mt = 0; mt < 2; mt++)
                    #pragma unroll
                    for (int nt = 0; nt < 8; nt++)
                        mma16816(acc[mt][nt], a[mt], b[nt >> 1][(nt & 1) << 1], b[nt >> 1][((nt & 1) << 1) + 1]);
            }
        }

        // all warps done reading W[mat]; overlap next-W load with epilogue
        if (mat < 2) {
            __syncthreads();
            const char* wsrc = (const char*)g_wh + ((size_t)(mat + 1) << 16);
            #pragma unroll
            for (int r = 0; r < 8; r++) {
                int idx = (r << 9) + tid;
                int h = idx >> 11;
                int rem = idx & 2047;
                int n = rem >> 4;
                int u = rem & 15;
                uint32_t dst = sbase + SM_WB + (h << 15) + (uint32_t)(n * 256 + ((u ^ (n & 7)) << 4));
                cp_async16(dst, wsrc + ((size_t)h << 15) + (size_t)n * 256 + (u << 4));
            }
            cp_commit();
        }

        // ---- epilogue for this mat ----
        {
            float* outp = (mat == 0) ? g_h : ((mat == 1) ? g_rate : g_gamma);
            const float* bias = (mat == 0) ? b_fc : b_rob;
            #pragma unroll
            for (int mt = 0; mt < 2; mt++) {
                int r0 = m0 + warpM * 32 + mt * 16 + g4;
                int r1 = r0 + 8;
                #pragma unroll
                for (int nt = 0; nt < 8; nt++) {
                    int col = warpN * 64 + nt * 8 + t4 * 2;
                    float v0 = acc[mt][nt][0], v1 = acc[mt][nt][1];
                    float v2 = acc[mt][nt][2], v3 = acc[mt][nt][3];
                    if (mat == 1) {
                        v0 = ((v0 > 20.f) ? v0 : log1pf(__expf(v0))) + EPSV;
                        v1 = ((v1 > 20.f) ? v1 : log1pf(__expf(v1))) + EPSV;
                        v2 = ((v2 > 20.f) ? v2 : log1pf(__expf(v2))) + EPSV;
                        v3 = ((v3 > 20.f) ? v3 : log1pf(__expf(v3))) + EPSV;
                    } else {
                        float b0 = bias[col], b1 = bias[col + 1];
                        v0 += b0; v1 += b1; v2 += b0; v3 += b1;
                    }
                    if (r0 < N_NODES) *(float2*)(outp + (size_t)r0 * D + col) = make_float2(v0, v1);
                    if (r1 < N_NODES) *(float2*)(outp + (size_t)r1 * D + col) = make_float2(v2, v3);
                }
            }
        }

        if (mat < 2) { cp_wait0(); __syncthreads(); }
    }
}

// ---------------- fused gather + combine + LayerNorm (one warp per node) ----
__global__ __launch_bounds__(256) void k_final(const int* __restrict__ degree,
                                               const float* __restrict__ ln_g,
                                               const float* __restrict__ ln_b,
                                               float* __restrict__ out)
{
    int w = (blockIdx.x * blockDim.x + threadIdx.x) >> 5;
    int lane = threadIdx.x & 31;
    if (w >= N_NODES) return;
    size_t base = (size_t)w * D;

    int start = g_off[w] + g_bsum[w >> 9];
    int cnt = g_cnt[w];

    float4 acc = make_float4(0.f, 0.f, 0.f, 0.f);
    int j = 0;
    for (; j + 4 <= cnt; j += 4) {
        int c0 = g_ecol[start + j + 0];
        int c1 = g_ecol[start + j + 1];
        int c2 = g_ecol[start + j + 2];
        int c3 = g_ecol[start + j + 3];
        float4 v0 = __ldg(((const float4*)(g_h + (size_t)c0 * D)) + lane);
        float4 v1 = __ldg(((const float4*)(g_h + (size_t)c1 * D)) + lane);
        float4 v2 = __ldg(((const float4*)(g_h + (size_t)c2 * D)) + lane);
        float4 v3 = __ldg(((const float4*)(g_h + (size_t)c3 * D)) + lane);
        acc.x += (v0.x + v1.x) + (v2.x + v3.x);
        acc.y += (v0.y + v1.y) + (v2.y + v3.y);
        acc.z += (v0.z + v1.z) + (v2.z + v3.z);
        acc.w += (v0.w + v1.w) + (v2.w + v3.w);
    }
    for (; j < cnt; j++) {
        int c = g_ecol[start + j];
        float4 v = __ldg(((const float4*)(g_h + (size_t)c * D)) + lane);
        acc.x += v.x; acc.y += v.y; acc.z += v.z; acc.w += v.w;
    }

    float4 h4 = ((const float4*)(g_h + base))[lane];
    float4 r4 = ((const float4*)(g_rate + base))[lane];
    float4 g4 = ((const float4*)(g_gamma + base))[lane];
    float fc = (float)cnt;
    float deg = (float)degree[w];

    float y[4];
    {
        const float* hp = (const float*)&h4;
        const float* ap = (const float*)&acc;
        const float* rp = (const float*)&r4;
        const float* gp = (const float*)&g4;
        #pragma unroll
        for (int i = 0; i < 4; i++) {
            float agg_full = ap[i] + fc * hp[i];
            y[i] = (rp[i] * agg_full + gp[i]) / (1.0f + EPSV + rp[i] * deg);
        }
    }

    float s = y[0] + y[1] + y[2] + y[3];
    float s2 = y[0]*y[0] + y[1]*y[1] + y[2]*y[2] + y[3]*y[3];
    #pragma unroll
    for (int off = 16; off > 0; off >>= 1) {
        s  += __shfl_xor_sync(0xffffffffu, s,  off);
        s2 += __shfl_xor_sync(0xffffffffu, s2, off);
    }
    float mean = s * (1.0f / D);
    float var = s2 * (1.0f / D) - mean * mean;
    float rstd = rsqrtf(var + LN_EPSV);

    float4 lg = ((const float4*)ln_g)[lane];
    float4 lb = ((const float4*)ln_b)[lane];
    float4 o;
    o.x = (y[0] - mean) * rstd * lg.x + lb.x;
    o.y = (y[1] - mean) * rstd * lg.y + lb.y;
    o.z = (y[2] - mean) * rstd * lg.z + lb.z;
    o.w = (y[3] - mean) * rstd * lg.w + lb.w;
    ((float4*)(out + base))[lane] = o;
}

// ---------------- launch ----------------
extern "C" void kernel_launch(void* const* d_in, const int* in_sizes, int n_in,
                              void* d_out, int out_size) {
    const float* x      = (const float*)d_in[0];
    const int*   ei     = (const int*)  d_in[1];
    const int*   degree = (const int*)  d_in[2];
    const float* W_fc   = (const float*)d_in[3];
    const float* b_fc   = (const float*)d_in[4];
    const float* W_rate = (const float*)d_in[5];
    const float* W_rob  = (const float*)d_in[6];
    const float* b_rob  = (const float*)d_in[7];
    const float* ln_g   = (const float*)d_in[8];
    const float* ln_b   = (const float*)d_in[9];
    float* out = (float*)d_out;

    const int* row = ei;             // edge_index[0]
    const int* col = ei + E_EDGES;   // edge_index[1]

    // one-time setup (outside capture on the first/correctness call)
    static cudaStream_t sideStream = nullptr;
    static cudaEvent_t evRoot = nullptr, evSide = nullptr;
    if (!sideStream) {
        cudaStreamCreateWithFlags(&sideStream, cudaStreamNonBlocking);
        cudaEventCreateWithFlags(&evRoot, cudaEventDisableTiming);
        cudaEventCreateWithFlags(&evSide, cudaEventDisableTiming);
        cudaFuncSetAttribute(k_mm, cudaFuncAttributeMaxDynamicSharedMemorySize, SM_TOTAL);
    }

    // fork: CSR build on side stream, GEMM on main stream
    cudaEventRecord(evRoot, 0);
    cudaStreamWaitEvent(sideStream, evRoot, 0);

    // side stream: CSR build chain
    k_zero<<<(N_NODES + 255) / 256, 256, 0, sideStream>>>();
    k_count<<<(E_EDGES + 255) / 256, 256, 0, sideStream>>>(row);
    k_scan1<<<NBLK, SCAN_B, 0, sideStream>>>();
    k_scan2<<<1, 256, 0, sideStream>>>();
    k_bin<<<(E_EDGES + 255) / 256, 256, 0, sideStream>>>(row, col);
    cudaEventRecord(evSide, sideStream);

    // main stream: weight split + tensor-core GEMM
    k_wsplit<<<(3 * 128 * 32 + 255) / 256, 256>>>(W_fc, W_rate, W_rob);
    k_mm<<<MM_CTAS, MM_THREADS, SM_TOTAL>>>(x, b_fc, b_rob);

    // join, then fused gather + LayerNorm
    cudaStreamWaitEvent(0, evSide, 0);
    k_final<<<(int)(((size_t)N_NODES * 32 + 255) / 256), 256>>>(degree, ln_g, ln_b, out);
}

// round 9
// speedup vs baseline: 2.3747x; 1.1334x over previous
#include <cuda_runtime.h>
#include <cuda_fp16.h>
#include <math.h>
#include <cstdint>

#define N_NODES 100000
#define E_EDGES 800000
#define D 128
#define EPSV 1e-4f
#define LN_EPSV 1e-5f

#define SCAN_B 512
#define NBLK ((N_NODES + SCAN_B - 1) / SCAN_B)   // 196

#define TILE_M 256
#define MM_CTAS ((N_NODES + TILE_M - 1) / TILE_M)  // 391
#define MM_THREADS 512

// ---- scratch (device globals; no allocation allowed) ----
__device__ float  g_h[(size_t)N_NODES * D];
__device__ float  g_rate[(size_t)N_NODES * D];
__device__ float  g_gamma[(size_t)N_NODES * D];
__device__ int    g_cnt[N_NODES];
__device__ int    g_cur[N_NODES];
__device__ int    g_off[N_NODES];
__device__ int    g_bsum[NBLK];
__device__ int    g_ecol[E_EDGES];
// fp16-split, transposed weights: [mat(3)][hi/lo(2)][n(128)][k(128)] halves
__device__ __half g_wh[3 * 2 * 128 * 128];

// ============================ helpers ============================
__device__ __forceinline__ uint32_t smem_u32(const void* p) {
    uint32_t a;
    asm("{ .reg .u64 t; cvta.to.shared.u64 t, %1; cvt.u32.u64 %0, t; }" : "=r"(a) : "l"(p));
    return a;
}

__device__ __forceinline__ void ldmatrix4(uint32_t* r, uint32_t addr) {
    asm volatile("ldmatrix.sync.aligned.m8n8.x4.shared.b16 {%0,%1,%2,%3}, [%4];"
                 : "=r"(r[0]), "=r"(r[1]), "=r"(r[2]), "=r"(r[3]) : "r"(addr));
}

__device__ __forceinline__ void mma16816(float* c, const uint32_t* a, uint32_t b0, uint32_t b1) {
    asm volatile("mma.sync.aligned.m16n8k16.row.col.f32.f16.f16.f32 "
                 "{%0,%1,%2,%3}, {%4,%5,%6,%7}, {%8,%9}, {%0,%1,%2,%3};"
                 : "+f"(c[0]), "+f"(c[1]), "+f"(c[2]), "+f"(c[3])
                 : "r"(a[0]), "r"(a[1]), "r"(a[2]), "r"(a[3]), "r"(b0), "r"(b1));
}

__device__ __forceinline__ void cp_async16(uint32_t saddr, const void* gaddr) {
    asm volatile("cp.async.cg.shared.global [%0], [%1], 16;" :: "r"(saddr), "l"(gaddr));
}
__device__ __forceinline__ void cp_commit() { asm volatile("cp.async.commit_group;"); }
__device__ __forceinline__ void cp_wait0()  { asm volatile("cp.async.wait_group 0;" ::: "memory"); }

// ============================ small kernels ============================
__global__ void k_zero() {
    int i = blockIdx.x * blockDim.x + threadIdx.x;
    if (i < N_NODES) g_cnt[i] = 0;
}

__global__ void k_count(const int* __restrict__ row) {
    int e = blockIdx.x * blockDim.x + threadIdx.x;
    if (e < E_EDGES) atomicAdd(&g_cnt[row[e]], 1);
}

__global__ __launch_bounds__(SCAN_B) void k_scan1() {
    __shared__ int wsum[SCAN_B / 32];
    int i = blockIdx.x * SCAN_B + threadIdx.x;
    int lane = threadIdx.x & 31, wid = threadIdx.x >> 5;
    int v = (i < N_NODES) ? g_cnt[i] : 0;
    if (i < N_NODES) g_cur[i] = 0;
    int s = v;
    #pragma unroll
    for (int o = 1; o < 32; o <<= 1) { int t = __shfl_up_sync(~0u, s, o); if (lane >= o) s += t; }
    if (lane == 31) wsum[wid] = s;
    __syncthreads();
    if (wid == 0) {
        int ws = (lane < SCAN_B / 32) ? wsum[lane] : 0;
        #pragma unroll
        for (int o = 1; o < SCAN_B / 32; o <<= 1) { int t = __shfl_up_sync(~0u, ws, o); if (lane >= o) ws += t; }
        if (lane < SCAN_B / 32) wsum[lane] = ws;
    }
    __syncthreads();
    int base = (wid > 0) ? wsum[wid - 1] : 0;
    if (i < N_NODES) g_off[i] = base + s - v;
    if (threadIdx.x == SCAN_B - 1) g_bsum[blockIdx.x] = base + s;
}

__global__ __launch_bounds__(256) void k_scan2() {
    __shared__ int wsum[8];
    int lane = threadIdx.x & 31, wid = threadIdx.x >> 5;
    int v = (threadIdx.x < NBLK) ? g_bsum[threadIdx.x] : 0;
    int s = v;
    #pragma unroll
    for (int o = 1; o < 32; o <<= 1) { int t = __shfl_up_sync(~0u, s, o); if (lane >= o) s += t; }
    if (lane == 31) wsum[wid] = s;
    __syncthreads();
    if (wid == 0) {
        int ws = (lane < 8) ? wsum[lane] : 0;
        #pragma unroll
        for (int o = 1; o < 8; o <<= 1) { int t = __shfl_up_sync(~0u, ws, o); if (lane >= o) ws += t; }
        if (lane < 8) wsum[lane] = ws;
    }
    __syncthreads();
    int base = (wid > 0) ? wsum[wid - 1] : 0;
    if (threadIdx.x < NBLK) g_bsum[threadIdx.x] = base + s - v;
}

// bin: pos = local_off + block_base + rank (scan3 folded in)
__global__ __launch_bounds__(256) void k_bin(const int* __restrict__ row, const int* __restrict__ col) {
    int e = blockIdx.x * blockDim.x + threadIdx.x;
    if (e >= E_EDGES) return;
    int r = row[e];
    int pos = g_off[r] + g_bsum[r >> 9] + atomicAdd(&g_cur[r], 1);
    g_ecol[pos] = col[e];
}

// ---- pre-transpose + fp16-split W into g_wh[mat][hi/lo][n][k] ----
__global__ __launch_bounds__(256) void k_wsplit(const float* __restrict__ W_fc,
                                                const float* __restrict__ W_rate,
                                                const float* __restrict__ W_rob) {
    int t = blockIdx.x * blockDim.x + threadIdx.x;   // 3*128*32 = 12288
    if (t >= 3 * 128 * 32) return;
    int mat = t >> 12;
    int n = (t & 4095) >> 5;
    int k0 = (t & 31) << 2;
    const float* W = (mat == 0) ? W_fc : ((mat == 1) ? W_rate : W_rob);
    __half hi[4], lo[4];
    #pragma unroll
    for (int i = 0; i < 4; i++) {
        float v = W[(size_t)(k0 + i) * D + n];
        __half h = __float2half_rn(v);
        hi[i] = h;
        lo[i] = __float2half_rn(v - __half2float(h));
    }
    size_t oh = ((size_t)(mat * 2 + 0) << 14) + (n << 7) + k0;
    size_t ol = ((size_t)(mat * 2 + 1) << 14) + (n << 7) + k0;
    *(uint2*)(g_wh + oh) = *(uint2*)hi;
    *(uint2*)(g_wh + ol) = *(uint2*)lo;
}

// ============================ mma.sync fused 3x GEMM ============================
// TILE_M=256, 512 threads (16 warps: 8 M-groups x 2 N-groups).
// 2-term split: x_hi * (W_hi + W_lo)  — x_lo term dropped (~1.4e-4 rel).
// smem: x_hi [0,64K)  Wbuf [64K,128K) single-buffered (hi 32K + lo 32K)
// fp16 [row][k] rows of 256B, 16B-unit swizzle: unit u -> u ^ (row & 7).
#define SM_XHI   0
#define SM_WB    65536
#define SM_TOTAL 131072

__global__ __launch_bounds__(MM_THREADS, 1) void k_mm(const float* __restrict__ x,
                                                      const float* __restrict__ b_fc,
                                                      const float* __restrict__ b_rob) {
    extern __shared__ char smem[];
    const uint32_t sbase = smem_u32(smem);
    const int tid = threadIdx.x;
    const int wid = tid >> 5;
    const int lane = tid & 31;
    const int m0 = blockIdx.x * TILE_M;
    const int warpM = wid & 7;     // rows 32*warpM .. +32
    const int warpN = wid >> 3;    // cols 64*warpN .. +64

    // ---- prefetch W[0] (hi+lo, 64KB = 4096 16B units, 8 per thread) ----
    {
        const char* wsrc = (const char*)g_wh;
        #pragma unroll
        for (int r = 0; r < 8; r++) {
            int idx = (r << 9) + tid;           // 0..4095
            int h = idx >> 11;
            int rem = idx & 2047;
            int n = rem >> 4;
            int u = rem & 15;
            uint32_t dst = sbase + SM_WB + (h << 15) + (uint32_t)(n * 256 + ((u ^ (n & 7)) << 4));
            cp_async16(dst, wsrc + ((size_t)h << 15) + (size_t)n * 256 + (u << 4));
        }
        cp_commit();
    }

    // ---- stage x tile as fp16 hi only (256 rows x 128 k) ----
    #pragma unroll
    for (int r = 0; r < 16; r++) {
        int idx = (r << 9) + tid;           // 0..8191
        int m = idx >> 5;
        int kq = idx & 31;                  // float4 index; k0 = kq*4
        float4 v = make_float4(0.f, 0.f, 0.f, 0.f);
        if (m0 + m < N_NODES) v = *(const float4*)(x + (size_t)(m0 + m) * D + (kq << 2));
        uint2 hp;
        hp.x = __half_as_ushort(__float2half_rn(v.x)) | ((uint32_t)__half_as_ushort(__float2half_rn(v.y)) << 16);
        hp.y = __half_as_ushort(__float2half_rn(v.z)) | ((uint32_t)__half_as_ushort(__float2half_rn(v.w)) << 16);
        int u = kq >> 1;                    // 16B unit
        int off8 = (kq & 1) << 3;
        uint32_t so = (uint32_t)(m * 256 + ((u ^ (m & 7)) << 4) + off8);
        *(uint2*)(smem + SM_XHI + so) = hp;
    }
    cp_wait0();
    __syncthreads();

    // per-thread ldmatrix address components
    const int rowA_off = (lane & 7) + (((lane >> 3) & 1) << 3);
    const int dA = lane >> 4;
    const int nB_off = (lane & 7) + (((lane >> 4) & 1) << 3);
    const int dB = (lane >> 3) & 1;

    int rowA[2], s7A[2];
    #pragma unroll
    for (int mt = 0; mt < 2; mt++) {
        int rr = warpM * 32 + mt * 16 + rowA_off;
        rowA[mt] = rr * 256; s7A[mt] = rr & 7;
    }
    int rowB[4], s7B[4];
    #pragma unroll
    for (int nt2 = 0; nt2 < 4; nt2++) {
        int nn = warpN * 64 + nt2 * 16 + nB_off;
        rowB[nt2] = nn * 256; s7B[nt2] = nn & 7;
    }

    const int g4 = lane >> 2;      // C-frag row within tile
    const int t4 = lane & 3;       // C-frag col pair

    for (int mat = 0; mat < 3; mat++) {
        float acc[2][8][4];
        #pragma unroll
        for (int mt = 0; mt < 2; mt++)
            #pragma unroll
            for (int nt = 0; nt < 8; nt++)
                #pragma unroll
                for (int i = 0; i < 4; i++) acc[mt][nt][i] = 0.f;

        #pragma unroll 1
        for (int term = 0; term < 2; term++) {
            const uint32_t abase = sbase + SM_XHI;
            const uint32_t bbase = sbase + SM_WB + ((term == 1) ? 32768u : 0u);
            #pragma unroll 1
            for (int ks = 0; ks < 8; ks++) {
                uint32_t a[2][4];
                #pragma unroll
                for (int mt = 0; mt < 2; mt++) {
                    int u = 2 * ks + dA;
                    ldmatrix4(a[mt], abase + rowA[mt] + ((u ^ s7A[mt]) << 4));
                }
                uint32_t b[4][4];
                #pragma unroll
                for (int nt2 = 0; nt2 < 4; nt2++) {
                    int u = 2 * ks + dB;
                    ldmatrix4(b[nt2], bbase + rowB[nt2] + ((u ^ s7B[nt2]) << 4));
                }
                #pragma unroll
                for (int mt = 0; mt < 2; mt++)
                    #pragma unroll
                    for (int nt = 0; nt < 8; nt++)
                        mma16816(acc[mt][nt], a[mt], b[nt >> 1][(nt & 1) << 1], b[nt >> 1][((nt & 1) << 1) + 1]);
            }
        }

        // all warps done reading W[mat]; overlap next-W load with epilogue
        if (mat < 2) {
            __syncthreads();
            const char* wsrc = (const char*)g_wh + ((size_t)(mat + 1) << 16);
            #pragma unroll
            for (int r = 0; r < 8; r++) {
                int idx = (r << 9) + tid;
                int h = idx >> 11;
                int rem = idx & 2047;
                int n = rem >> 4;
                int u = rem & 15;
                uint32_t dst = sbase + SM_WB + (h << 15) + (uint32_t)(n * 256 + ((u ^ (n & 7)) << 4));
                cp_async16(dst, wsrc + ((size_t)h << 15) + (size_t)n * 256 + (u << 4));
            }
            cp_commit();
        }

        // ---- epilogue for this mat ----
        {
            float* outp = (mat == 0) ? g_h : ((mat == 1) ? g_rate : g_gamma);
            const float* bias = (mat == 0) ? b_fc : b_rob;
            #pragma unroll
            for (int mt = 0; mt < 2; mt++) {
                int r0 = m0 + warpM * 32 + mt * 16 + g4;
                int r1 = r0 + 8;
                #pragma unroll
                for (int nt = 0; nt < 8; nt++) {
                    int col = warpN * 64 + nt * 8 + t4 * 2;
                    float v0 = acc[mt][nt][0], v1 = acc[mt][nt][1];
                    float v2 = acc[mt][nt][2], v3 = acc[mt][nt][3];
                    if (mat == 1) {
                        v0 = ((v0 > 20.f) ? v0 : log1pf(__expf(v0))) + EPSV;
                        v1 = ((v1 > 20.f) ? v1 : log1pf(__expf(v1))) + EPSV;
                        v2 = ((v2 > 20.f) ? v2 : log1pf(__expf(v2))) + EPSV;
                        v3 = ((v3 > 20.f) ? v3 : log1pf(__expf(v3))) + EPSV;
                    } else {
                        float b0 = bias[col], b1 = bias[col + 1];
                        v0 += b0; v1 += b1; v2 += b0; v3 += b1;
                    }
                    if (r0 < N_NODES) *(float2*)(outp + (size_t)r0 * D + col) = make_float2(v0, v1);
                    if (r1 < N_NODES) *(float2*)(outp + (size_t)r1 * D + col) = make_float2(v2, v3);
                }
            }
        }

        if (mat < 2) { cp_wait0(); __syncthreads(); }
    }
}

// ---------------- fused gather + combine + LayerNorm (one warp per node) ----
__global__ __launch_bounds__(256) void k_final(const int* __restrict__ degree,
                                               const float* __restrict__ ln_g,
                                               const float* __restrict__ ln_b,
                                               float* __restrict__ out)
{
    int w = (blockIdx.x * blockDim.x + threadIdx.x) >> 5;
    int lane = threadIdx.x & 31;
    if (w >= N_NODES) return;
    size_t base = (size_t)w * D;

    int start = g_off[w] + g_bsum[w >> 9];
    int cnt = g_cnt[w];

    float4 acc = make_float4(0.f, 0.f, 0.f, 0.f);
    int j = 0;
    for (; j + 4 <= cnt; j += 4) {
        int c0 = g_ecol[start + j + 0];
        int c1 = g_ecol[start + j + 1];
        int c2 = g_ecol[start + j + 2];
        int c3 = g_ecol[start + j + 3];
        float4 v0 = __ldg(((const float4*)(g_h + (size_t)c0 * D)) + lane);
        float4 v1 = __ldg(((const float4*)(g_h + (size_t)c1 * D)) + lane);
        float4 v2 = __ldg(((const float4*)(g_h + (size_t)c2 * D)) + lane);
        float4 v3 = __ldg(((const float4*)(g_h + (size_t)c3 * D)) + lane);
        acc.x += (v0.x + v1.x) + (v2.x + v3.x);
        acc.y += (v0.y + v1.y) + (v2.y + v3.y);
        acc.z += (v0.z + v1.z) + (v2.z + v3.z);
        acc.w += (v0.w + v1.w) + (v2.w + v3.w);
    }
    for (; j < cnt; j++) {
        int c = g_ecol[start + j];
        float4 v = __ldg(((const float4*)(g_h + (size_t)c * D)) + lane);
        acc.x += v.x; acc.y += v.y; acc.z += v.z; acc.w += v.w;
    }

    float4 h4 = ((const float4*)(g_h + base))[lane];
    float4 r4 = ((const float4*)(g_rate + base))[lane];
    float4 g4 = ((const float4*)(g_gamma + base))[lane];
    float fc = (float)cnt;
    float deg = (float)degree[w];

    float y[4];
    {
        const float* hp = (const float*)&h4;
        const float* ap = (const float*)&acc;
        const float* rp = (const float*)&r4;
        const float* gp = (const float*)&g4;
        #pragma unroll
        for (int i = 0; i < 4; i++) {
            float agg_full = ap[i] + fc * hp[i];
            y[i] = (rp[i] * agg_full + gp[i]) / (1.0f + EPSV + rp[i] * deg);
        }
    }

    float s = y[0] + y[1] + y[2] + y[3];
    float s2 = y[0]*y[0] + y[1]*y[1] + y[2]*y[2] + y[3]*y[3];
    #pragma unroll
    for (int off = 16; off > 0; off >>= 1) {
        s  += __shfl_xor_sync(0xffffffffu, s,  off);
        s2 += __shfl_xor_sync(0xffffffffu, s2, off);
    }
    float mean = s * (1.0f / D);
    float var = s2 * (1.0f / D) - mean * mean;
    float rstd = rsqrtf(var + LN_EPSV);

    float4 lg = ((const float4*)ln_g)[lane];
    float4 lb = ((const float4*)ln_b)[lane];
    float4 o;
    o.x = (y[0] - mean) * rstd * lg.x + lb.x;
    o.y = (y[1] - mean) * rstd * lg.y + lb.y;
    o.z = (y[2] - mean) * rstd * lg.z + lb.z;
    o.w = (y[3] - mean) * rstd * lg.w + lb.w;
    ((float4*)(out + base))[lane] = o;
}

// ---------------- launch ----------------
extern "C" void kernel_launch(void* const* d_in, const int* in_sizes, int n_in,
                              void* d_out, int out_size) {
    const float* x      = (const float*)d_in[0];
    const int*   ei     = (const int*)  d_in[1];
    const int*   degree = (const int*)  d_in[2];
    const float* W_fc   = (const float*)d_in[3];
    const float* b_fc   = (const float*)d_in[4];
    const float* W_rate = (const float*)d_in[5];
    const float* W_rob  = (const float*)d_in[6];
    const float* b_rob  = (const float*)d_in[7];
    const float* ln_g   = (const float*)d_in[8];
    const float* ln_b   = (const float*)d_in[9];
    float* out = (float*)d_out;

    const int* row = ei;             // edge_index[0]
    const int* col = ei + E_EDGES;   // edge_index[1]

    // one-time setup (outside capture on the first/correctness call)
    static cudaStream_t sideStream = nullptr;
    static cudaEvent_t evRoot = nullptr, evSide = nullptr;
    if (!sideStream) {
        cudaStreamCreateWithFlags(&sideStream, cudaStreamNonBlocking);
        cudaEventCreateWithFlags(&evRoot, cudaEventDisableTiming);
        cudaEventCreateWithFlags(&evSide, cudaEventDisableTiming);
        cudaFuncSetAttribute(k_mm, cudaFuncAttributeMaxDynamicSharedMemorySize, SM_TOTAL);
    }

    // fork: CSR build on side stream, GEMM on main stream
    cudaEventRecord(evRoot, 0);
    cudaStreamWaitEvent(sideStream, evRoot, 0);

    // side stream: CSR build chain
    k_zero<<<(N_NODES + 255) / 256, 256, 0, sideStream>>>();
    k_count<<<(E_EDGES + 255) / 256, 256, 0, sideStream>>>(row);
    k_scan1<<<NBLK, SCAN_B, 0, sideStream>>>();
    k_scan2<<<1, 256, 0, sideStream>>>();
    k_bin<<<(E_EDGES + 255) / 256, 256, 0, sideStream>>>(row, col);
    cudaEventRecord(evSide, sideStream);

    // main stream: weight split + tensor-core GEMM
    k_wsplit<<<(3 * 128 * 32 + 255) / 256, 256>>>(W_fc, W_rate, W_rob);
    k_mm<<<MM_CTAS, MM_THREADS, SM_TOTAL>>>(x, b_fc, b_rob);

    // join, then fused gather + LayerNorm
    cudaStreamWaitEvent(0, evSide, 0);
    k_final<<<(int)(((size_t)N_NODES * 32 + 255) / 256), 256>>>(degree, ln_g, ln_b, out);
}